// round 11
// baseline (speedup 1.0000x reference)
#include <cuda_runtime.h>
#include <math.h>

// Problem shape (fixed by the reference)
#define B_ 16
#define S_ 2048
#define D_ 512
#define QSPLIT 8

// ---------------------------------------------------------------------------
// Scratch (device globals: allocation-free per harness rules)
// ---------------------------------------------------------------------------
__device__ float g_G[D_ * D_];                       // Wq @ Wk^T / sqrt(D)   (1 MB)
__device__ float g_H[B_ * S_ * D_];                  // X @ G                 (64 MB)
__device__ float g_S[67108864];                      // B*S*S scores          (256 MB)
__device__ float g_m[B_ * S_];                       // row max
__device__ float g_linv[B_ * S_];                    // 1 / row sumexp
__device__ float g_c[B_ * S_];                       // column sums of softmax
__device__ float g_tp[QSPLIT * B_ * D_];             // partial c@X
__device__ float g_t[B_ * D_];                       // c@X

// ---------------------------------------------------------------------------
// Packed f32x2 helpers (FFMA2: 2x fp32 FMA throughput on sm_103a)
// ---------------------------------------------------------------------------
typedef unsigned long long u64;

__device__ __forceinline__ u64 ffma2(u64 a, u64 b, u64 c) {
    u64 r;
    asm("fma.rn.f32x2 %0, %1, %2, %3;" : "=l"(r) : "l"(a), "l"(b), "l"(c));
    return r;
}
__device__ __forceinline__ u64 fdup(float x) {
    u64 r;
    unsigned xi = __float_as_uint(x);
    asm("mov.b64 %0, {%1, %1};" : "=l"(r) : "r"(xi));
    return r;
}
__device__ __forceinline__ float2 unpack2(u64 v) {
    unsigned lo, hi;
    asm("mov.b64 {%0, %1}, %2;" : "=r"(lo), "=r"(hi) : "l"(v));
    return make_float2(__uint_as_float(lo), __uint_as_float(hi));
}

// ---------------------------------------------------------------------------
// fp32x2 SGEMM, 128x128 tile, BK=8, 256 threads, 8x8 per thread (2x2 quadrants)
// ---------------------------------------------------------------------------
#define TILE 128
#define BKD 8
#define SLD (TILE + 4)   // padded smem row: conflict-free transposed stores

// C[M,N] = alpha * A[M,K] @ B[K,N]   (all row-major). M = gridDim.y*128.
__global__ __launch_bounds__(256, 2)
void sgemm_nn_k(const float* __restrict__ A, const float* __restrict__ Bm,
                float* __restrict__ C, int K, int N, float alpha)
{
    __shared__ __align__(16) float As[BKD][SLD];
    __shared__ __align__(16) float Bs[BKD][SLD];
    const int tid = threadIdx.x;
    const int tx = tid & 15;
    const int ty = tid >> 4;
    const int m0 = blockIdx.y * TILE;
    const int n0 = blockIdx.x * TILE;

    const int arow = tid >> 1;          // 0..127
    const int acol = (tid & 1) << 2;    // 0 or 4
    const int brow = tid >> 5;          // 0..7
    const int bcol = (tid & 31) << 2;   // 0..124

    const float* Ap = A + (size_t)(m0 + arow) * K + acol;
    const float* Bp = Bm + (size_t)brow * N + (n0 + bcol);

    u64 acc[8][4];
#pragma unroll
    for (int i = 0; i < 8; i++)
#pragma unroll
        for (int j = 0; j < 4; j++) acc[i][j] = 0ull;

    float4 av = *(const float4*)(Ap);
    float4 bv = *(const float4*)(Bp);

    for (int k0 = 0; k0 < K; k0 += BKD) {
        As[acol + 0][arow] = av.x;
        As[acol + 1][arow] = av.y;
        As[acol + 2][arow] = av.z;
        As[acol + 3][arow] = av.w;
        *(float4*)&Bs[brow][bcol] = bv;
        __syncthreads();
        if (k0 + BKD < K) {               // prefetch next tiles
            av = *(const float4*)(Ap + k0 + BKD);
            bv = *(const float4*)(Bp + (size_t)(k0 + BKD) * N);
        }
#pragma unroll
        for (int kk = 0; kk < BKD; kk++) {
            float4 a0 = *(const float4*)&As[kk][ty << 2];
            float4 a1 = *(const float4*)&As[kk][64 + (ty << 2)];
            const u64* bq0 = (const u64*)&Bs[kk][tx << 2];
            const u64* bq1 = (const u64*)&Bs[kk][64 + (tx << 2)];
            u64 b0 = bq0[0], b1 = bq0[1], b2 = bq1[0], b3 = bq1[1];
            float a[8] = {a0.x, a0.y, a0.z, a0.w, a1.x, a1.y, a1.z, a1.w};
#pragma unroll
            for (int i = 0; i < 8; i++) {
                u64 ad = fdup(a[i]);
                acc[i][0] = ffma2(ad, b0, acc[i][0]);
                acc[i][1] = ffma2(ad, b1, acc[i][1]);
                acc[i][2] = ffma2(ad, b2, acc[i][2]);
                acc[i][3] = ffma2(ad, b3, acc[i][3]);
            }
        }
        __syncthreads();
    }
#pragma unroll
    for (int i = 0; i < 8; i++) {
        int rr = (i < 4) ? ((ty << 2) + i) : ((ty << 2) + 60 + i);
        float* crow = C + (size_t)(m0 + rr) * N + n0;
        float2 p0 = unpack2(acc[i][0]), p1 = unpack2(acc[i][1]);
        float2 p2 = unpack2(acc[i][2]), p3 = unpack2(acc[i][3]);
        float4 v0 = make_float4(alpha * p0.x, alpha * p0.y, alpha * p1.x, alpha * p1.y);
        float4 v1 = make_float4(alpha * p2.x, alpha * p2.y, alpha * p3.x, alpha * p3.y);
        *(float4*)(crow + (tx << 2)) = v0;
        *(float4*)(crow + 64 + (tx << 2)) = v1;
    }
}

// C[M,N] = alpha * A[M,K] @ B[N,K]^T  (row-major, batched via blockIdx.z strides)
__global__ __launch_bounds__(256, 2)
void sgemm_nt_k(const float* __restrict__ A, const float* __restrict__ Bm,
                float* __restrict__ C, int K, int N, float alpha,
                long long sA, long long sB, long long sC)
{
    __shared__ __align__(16) float As[BKD][SLD];
    __shared__ __align__(16) float Bs[BKD][SLD];
    const int tid = threadIdx.x;
    const int tx = tid & 15;
    const int ty = tid >> 4;
    const int m0 = blockIdx.y * TILE;
    const int n0 = blockIdx.x * TILE;

    const float* Ab = A + (size_t)blockIdx.z * (size_t)sA;
    const float* Bb = Bm + (size_t)blockIdx.z * (size_t)sB;
    float* Cb = C + (size_t)blockIdx.z * (size_t)sC;

    const int lrow = tid >> 1;          // 0..127
    const int lcol = (tid & 1) << 2;    // 0 or 4

    const float* Ap = Ab + (size_t)(m0 + lrow) * K + lcol;
    const float* Bp = Bb + (size_t)(n0 + lrow) * K + lcol;

    u64 acc[8][4];
#pragma unroll
    for (int i = 0; i < 8; i++)
#pragma unroll
        for (int j = 0; j < 4; j++) acc[i][j] = 0ull;

    float4 av = *(const float4*)(Ap);
    float4 bv = *(const float4*)(Bp);

    for (int k0 = 0; k0 < K; k0 += BKD) {
        As[lcol + 0][lrow] = av.x;
        As[lcol + 1][lrow] = av.y;
        As[lcol + 2][lrow] = av.z;
        As[lcol + 3][lrow] = av.w;
        Bs[lcol + 0][lrow] = bv.x;
        Bs[lcol + 1][lrow] = bv.y;
        Bs[lcol + 2][lrow] = bv.z;
        Bs[lcol + 3][lrow] = bv.w;
        __syncthreads();
        if (k0 + BKD < K) {
            av = *(const float4*)(Ap + k0 + BKD);
            bv = *(const float4*)(Bp + k0 + BKD);
        }
#pragma unroll
        for (int kk = 0; kk < BKD; kk++) {
            float4 a0 = *(const float4*)&As[kk][ty << 2];
            float4 a1 = *(const float4*)&As[kk][64 + (ty << 2)];
            const u64* bq0 = (const u64*)&Bs[kk][tx << 2];
            const u64* bq1 = (const u64*)&Bs[kk][64 + (tx << 2)];
            u64 b0 = bq0[0], b1 = bq0[1], b2 = bq1[0], b3 = bq1[1];
            float a[8] = {a0.x, a0.y, a0.z, a0.w, a1.x, a1.y, a1.z, a1.w};
#pragma unroll
            for (int i = 0; i < 8; i++) {
                u64 ad = fdup(a[i]);
                acc[i][0] = ffma2(ad, b0, acc[i][0]);
                acc[i][1] = ffma2(ad, b1, acc[i][1]);
                acc[i][2] = ffma2(ad, b2, acc[i][2]);
                acc[i][3] = ffma2(ad, b3, acc[i][3]);
            }
        }
        __syncthreads();
    }
#pragma unroll
    for (int i = 0; i < 8; i++) {
        int rr = (i < 4) ? ((ty << 2) + i) : ((ty << 2) + 60 + i);
        float* crow = Cb + (size_t)(m0 + rr) * N + n0;
        float2 p0 = unpack2(acc[i][0]), p1 = unpack2(acc[i][1]);
        float2 p2 = unpack2(acc[i][2]), p3 = unpack2(acc[i][3]);
        float4 v0 = make_float4(alpha * p0.x, alpha * p0.y, alpha * p1.x, alpha * p1.y);
        float4 v1 = make_float4(alpha * p2.x, alpha * p2.y, alpha * p3.x, alpha * p3.y);
        *(float4*)(crow + (tx << 2)) = v0;
        *(float4*)(crow + 64 + (tx << 2)) = v1;
    }
}

// ---------------------------------------------------------------------------
// Softmax row stats: per row (b,q) of g_S compute max and 1/sumexp
// ---------------------------------------------------------------------------
__global__ void row_stats_k()
{
    const int row = blockIdx.x;                 // 0 .. B*S-1
    const float* r = g_S + (size_t)row * S_;
    const int tid = threadIdx.x;                // 256 threads

    float v[8];
    float mx = -3.0e38f;
#pragma unroll
    for (int i = 0; i < 8; i++) {
        v[i] = r[i * 256 + tid];
        mx = fmaxf(mx, v[i]);
    }
    __shared__ float red[8];
#pragma unroll
    for (int o = 16; o > 0; o >>= 1) mx = fmaxf(mx, __shfl_xor_sync(0xffffffffu, mx, o));
    if ((tid & 31) == 0) red[tid >> 5] = mx;
    __syncthreads();
    float m = red[0];
#pragma unroll
    for (int w = 1; w < 8; w++) m = fmaxf(m, red[w]);
    __syncthreads();

    float s = 0.f;
#pragma unroll
    for (int i = 0; i < 8; i++) s += __expf(v[i] - m);
#pragma unroll
    for (int o = 16; o > 0; o >>= 1) s += __shfl_xor_sync(0xffffffffu, s, o);
    if ((tid & 31) == 0) red[tid >> 5] = s;
    __syncthreads();
    if (tid == 0) {
        float t = 0.f;
#pragma unroll
        for (int w = 0; w < 8; w++) t += red[w];
        g_m[row] = m;
        g_linv[row] = 1.0f / t;
    }
}

// ---------------------------------------------------------------------------
// Column sums of softmax: c[b,k] = sum_q exp(S[b,q,k]-m[b,q]) * linv[b,q]
// ---------------------------------------------------------------------------
__global__ void colsum_k()
{
    const int b = blockIdx.y;
    const int k = blockIdx.x * 256 + threadIdx.x;
    const float* Sb = g_S + (size_t)b * S_ * S_;
    const float* mb = g_m + b * S_;
    const float* lb = g_linv + b * S_;
    float acc = 0.f;
#pragma unroll 4
    for (int q = 0; q < S_; q++) {
        acc += __expf(Sb[(size_t)q * S_ + k] - mb[q]) * lb[q];
    }
    g_c[b * S_ + k] = acc;
}

// ---------------------------------------------------------------------------
// Partial t = c @ X  (per q-chunk), then reduce, then out = t @ Wv
// ---------------------------------------------------------------------------
__global__ void cx_k(const float* __restrict__ X)
{
    const int b = blockIdx.z;
    const int p = blockIdx.y;
    const int d = blockIdx.x * 256 + threadIdx.x;
    const float* Xb = X + (size_t)b * S_ * D_;
    const float* cb = g_c + b * S_;
    const int q0 = p * (S_ / QSPLIT);
    float acc = 0.f;
#pragma unroll 4
    for (int i = 0; i < S_ / QSPLIT; i++) {
        int q = q0 + i;
        acc += cb[q] * Xb[(size_t)q * D_ + d];
    }
    g_tp[(p * B_ + b) * D_ + d] = acc;
}

__global__ void reduce_t_k()
{
    const int b = blockIdx.x;
    const int d = threadIdx.x;
    float s = 0.f;
#pragma unroll
    for (int p = 0; p < QSPLIT; p++) s += g_tp[(p * B_ + b) * D_ + d];
    g_t[b * D_ + d] = s;
}

__global__ void out_k(const float* __restrict__ Wv, float* __restrict__ out)
{
    const int b = blockIdx.y;
    const int e = blockIdx.x * 128 + threadIdx.x;
    const float* tb = g_t + b * D_;
    float acc = 0.f;
#pragma unroll 8
    for (int d = 0; d < D_; d++)
        acc += tb[d] * Wv[(size_t)d * D_ + e];
    out[b * D_ + e] = acc;
}

// ---------------------------------------------------------------------------
// Launch: G = Wq Wk^T/sqrt(D); H = X G; S = H X^T; softmax stats; colsum;
//         t = c X; out = t Wv.   All graph-capturable, allocation-free.
// ---------------------------------------------------------------------------
extern "C" void kernel_launch(void* const* d_in, const int* in_sizes, int n_in,
                              void* d_out, int out_size)
{
    const float* X  = (const float*)d_in[0];
    const float* Wq = (const float*)d_in[1];
    const float* Wk = (const float*)d_in[2];
    const float* Wv = (const float*)d_in[3];
    float* out = (float*)d_out;

    float *pG = nullptr, *pH = nullptr, *pS = nullptr;
    cudaGetSymbolAddress((void**)&pG, g_G);
    cudaGetSymbolAddress((void**)&pH, g_H);
    cudaGetSymbolAddress((void**)&pS, g_S);

    const float inv_sqrt_d = 1.0f / sqrtf((float)D_);

    // G = (Wq @ Wk^T) / sqrt(D)           [512 x 512]
    sgemm_nt_k<<<dim3(D_ / 128, D_ / 128, 1), 256>>>(
        Wq, Wk, pG, D_, D_, inv_sqrt_d, 0, 0, 0);

    // H = X @ G                           [B*S x 512]
    sgemm_nn_k<<<dim3(D_ / 128, (B_ * S_) / 128, 1), 256>>>(
        X, pG, pH, D_, D_, 1.0f);

    // S_b = H_b @ X_b^T                   [B x S x S]  (scale already in G)
    sgemm_nt_k<<<dim3(S_ / 128, S_ / 128, B_), 256>>>(
        pH, X, pS, D_, S_, 1.0f,
        (long long)S_ * D_, (long long)S_ * D_, (long long)S_ * S_);

    // Softmax row stats + column sums
    row_stats_k<<<B_ * S_, 256>>>();
    colsum_k<<<dim3(S_ / 256, B_), 256>>>();

    // t = c @ X (partials over q-chunks, deterministic reduce)
    cx_k<<<dim3(D_ / 256, QSPLIT, B_), 256>>>(X);
    reduce_t_k<<<B_, D_>>>();

    // out = t @ Wv
    out_k<<<dim3(D_ / 128, B_), 128>>>(Wv, out);
}

// round 16
// speedup vs baseline: 1.4621x; 1.4621x over previous
#include <cuda_runtime.h>
#include <cuda_bf16.h>
#include <stdint.h>
#include <math.h>

// Problem shape (fixed by the reference)
#define B_ 16
#define S_ 2048
#define D_ 512
#define QSPLIT 8

// ---------------------------------------------------------------------------
// Scratch (device globals: allocation-free per harness rules)
// ---------------------------------------------------------------------------
__device__ float g_G[D_ * D_];                        // Gt = Wk @ Wq^T / sqrt(D)
__device__ float g_S[67108864];                       // B*S*S scores (256 MB)
__device__ float g_m[B_ * S_];                        // row max
__device__ float g_linv[B_ * S_];                     // 1 / row sumexp
__device__ float g_c[B_ * S_];                        // column sums of softmax
__device__ float g_tp[QSPLIT * B_ * D_];              // partial c@X
__device__ float g_t[B_ * D_];                        // c@X
__device__ __nv_bfloat16 g_Xh[B_ * S_ * D_];          // X hi (32 MB)
__device__ __nv_bfloat16 g_Xl[B_ * S_ * D_];          // X lo
__device__ __nv_bfloat16 g_Hh[B_ * S_ * D_];          // H hi
__device__ __nv_bfloat16 g_Hl[B_ * S_ * D_];          // H lo
__device__ __nv_bfloat16 g_Gth[D_ * D_];              // Gt hi
__device__ __nv_bfloat16 g_Gtl[D_ * D_];              // Gt lo

// ---------------------------------------------------------------------------
// Packed f32x2 helpers (for the tiny fp32 Gt GEMM)
// ---------------------------------------------------------------------------
typedef unsigned long long u64;

__device__ __forceinline__ u64 ffma2(u64 a, u64 b, u64 c) {
    u64 r;
    asm("fma.rn.f32x2 %0, %1, %2, %3;" : "=l"(r) : "l"(a), "l"(b), "l"(c));
    return r;
}
__device__ __forceinline__ u64 fdup(float x) {
    u64 r;
    unsigned xi = __float_as_uint(x);
    asm("mov.b64 %0, {%1, %1};" : "=l"(r) : "r"(xi));
    return r;
}
__device__ __forceinline__ float2 unpack2(u64 v) {
    unsigned lo, hi;
    asm("mov.b64 {%0, %1}, %2;" : "=r"(lo), "=r"(hi) : "l"(v));
    return make_float2(__uint_as_float(lo), __uint_as_float(hi));
}

// ---------------------------------------------------------------------------
// fp32x2 SGEMM nt (only used for Gt = Wk @ Wq^T, 512x512)
// ---------------------------------------------------------------------------
#define TILE 128
#define BKD 8
#define SLD (TILE + 4)

__global__ __launch_bounds__(256, 2)
void sgemm_nt_k(const float* __restrict__ A, const float* __restrict__ Bm,
                float* __restrict__ C, int K, int N, float alpha)
{
    __shared__ __align__(16) float As[BKD][SLD];
    __shared__ __align__(16) float Bs[BKD][SLD];
    const int tid = threadIdx.x;
    const int tx = tid & 15;
    const int ty = tid >> 4;
    const int m0 = blockIdx.y * TILE;
    const int n0 = blockIdx.x * TILE;

    const int lrow = tid >> 1;
    const int lcol = (tid & 1) << 2;

    const float* Ap = A + (size_t)(m0 + lrow) * K + lcol;
    const float* Bp = Bm + (size_t)(n0 + lrow) * K + lcol;

    u64 acc[8][4];
#pragma unroll
    for (int i = 0; i < 8; i++)
#pragma unroll
        for (int j = 0; j < 4; j++) acc[i][j] = 0ull;

    float4 av = *(const float4*)(Ap);
    float4 bv = *(const float4*)(Bp);

    for (int k0 = 0; k0 < K; k0 += BKD) {
        As[lcol + 0][lrow] = av.x; As[lcol + 1][lrow] = av.y;
        As[lcol + 2][lrow] = av.z; As[lcol + 3][lrow] = av.w;
        Bs[lcol + 0][lrow] = bv.x; Bs[lcol + 1][lrow] = bv.y;
        Bs[lcol + 2][lrow] = bv.z; Bs[lcol + 3][lrow] = bv.w;
        __syncthreads();
        if (k0 + BKD < K) {
            av = *(const float4*)(Ap + k0 + BKD);
            bv = *(const float4*)(Bp + k0 + BKD);
        }
#pragma unroll
        for (int kk = 0; kk < BKD; kk++) {
            float4 a0 = *(const float4*)&As[kk][ty << 2];
            float4 a1 = *(const float4*)&As[kk][64 + (ty << 2)];
            const u64* bq0 = (const u64*)&Bs[kk][tx << 2];
            const u64* bq1 = (const u64*)&Bs[kk][64 + (tx << 2)];
            u64 b0 = bq0[0], b1 = bq0[1], b2 = bq1[0], b3 = bq1[1];
            float a[8] = {a0.x, a0.y, a0.z, a0.w, a1.x, a1.y, a1.z, a1.w};
#pragma unroll
            for (int i = 0; i < 8; i++) {
                u64 ad = fdup(a[i]);
                acc[i][0] = ffma2(ad, b0, acc[i][0]);
                acc[i][1] = ffma2(ad, b1, acc[i][1]);
                acc[i][2] = ffma2(ad, b2, acc[i][2]);
                acc[i][3] = ffma2(ad, b3, acc[i][3]);
            }
        }
        __syncthreads();
    }
#pragma unroll
    for (int i = 0; i < 8; i++) {
        int rr = (i < 4) ? ((ty << 2) + i) : ((ty << 2) + 60 + i);
        float* crow = C + (size_t)(m0 + rr) * N + n0;
        float2 p0 = unpack2(acc[i][0]), p1 = unpack2(acc[i][1]);
        float2 p2 = unpack2(acc[i][2]), p3 = unpack2(acc[i][3]);
        float4 v0 = make_float4(alpha * p0.x, alpha * p0.y, alpha * p1.x, alpha * p1.y);
        float4 v1 = make_float4(alpha * p2.x, alpha * p2.y, alpha * p3.x, alpha * p3.y);
        *(float4*)(crow + (tx << 2)) = v0;
        *(float4*)(crow + 64 + (tx << 2)) = v1;
    }
}

// ---------------------------------------------------------------------------
// fp32 -> bf16 hi/lo split (vectorized by 4)
// ---------------------------------------------------------------------------
__global__ void split4_k(const float4* __restrict__ src,
                         __nv_bfloat162* __restrict__ hi,
                         __nv_bfloat162* __restrict__ lo, int n4)
{
    int i = blockIdx.x * 256 + threadIdx.x;
    if (i >= n4) return;
    float4 v = src[i];
    __nv_bfloat16 h0 = __float2bfloat16(v.x), h1 = __float2bfloat16(v.y);
    __nv_bfloat16 h2 = __float2bfloat16(v.z), h3 = __float2bfloat16(v.w);
    __nv_bfloat16 l0 = __float2bfloat16(v.x - __bfloat162float(h0));
    __nv_bfloat16 l1 = __float2bfloat16(v.y - __bfloat162float(h1));
    __nv_bfloat16 l2 = __float2bfloat16(v.z - __bfloat162float(h2));
    __nv_bfloat16 l3 = __float2bfloat16(v.w - __bfloat162float(h3));
    __nv_bfloat162 a; a.x = h0; a.y = h1;
    __nv_bfloat162 b; b.x = h2; b.y = h3;
    __nv_bfloat162 c; c.x = l0; c.y = l1;
    __nv_bfloat162 d; d.x = l2; d.y = l3;
    hi[2 * i] = a; hi[2 * i + 1] = b;
    lo[2 * i] = c; lo[2 * i + 1] = d;
}

// ---------------------------------------------------------------------------
// HMMA (mma.sync m16n8k16 bf16) split NT GEMM.
// C = Ahi Bhi^T + Ahi Blo^T + Alo Bhi^T,  fp32 accumulate.
// A: [M,K] K-major, B: [N,K] K-major (both bf16 hi/lo).
// CTA tile 128x128, 8 warps = 4(M) x 2(N) -> warp tile 32x64.
// KC=32 double-buffered via cp.async; smem row stride 40 halves
// (conflict-free for ldmatrix: bank start 20*r mod 32 covers all banks).
// epi=0: fp32 C out.  epi=1: bf16 hi/lo out (Ch/Cl).
// ---------------------------------------------------------------------------
#define STRH 40                       // halves per smem row
#define MATSZ (128 * STRH * 2)        // 10240 B per matrix tile
#define HSTAGE (4 * MATSZ)            // 40960 B per stage
#define HSMEM (2 * HSTAGE)            // 81920 B total

static __device__ __forceinline__ uint32_t s2u(const void* p) {
    uint32_t a;
    asm("{ .reg .u64 t; cvta.to.shared.u64 t, %1; cvt.u32.u64 %0, t; }" : "=r"(a) : "l"(p));
    return a;
}
static __device__ __forceinline__ void cpa16(uint32_t s, const void* g) {
    asm volatile("cp.async.cg.shared.global [%0], [%1], 16;" :: "r"(s), "l"(g));
}
static __device__ __forceinline__ void ldm4(uint32_t* r, uint32_t a) {
    asm volatile("ldmatrix.sync.aligned.m8n8.x4.shared.b16 {%0,%1,%2,%3}, [%4];"
                 : "=r"(r[0]), "=r"(r[1]), "=r"(r[2]), "=r"(r[3]) : "r"(a));
}
static __device__ __forceinline__ void mma16816(float* d, const uint32_t* a,
                                                uint32_t b0, uint32_t b1) {
    asm volatile("mma.sync.aligned.m16n8k16.row.col.f32.bf16.bf16.f32 "
                 "{%0,%1,%2,%3}, {%4,%5,%6,%7}, {%8,%9}, {%0,%1,%2,%3};"
                 : "+f"(d[0]), "+f"(d[1]), "+f"(d[2]), "+f"(d[3])
                 : "r"(a[0]), "r"(a[1]), "r"(a[2]), "r"(a[3]), "r"(b0), "r"(b1));
}
static __device__ __forceinline__ unsigned short bfu(float f) {
    __nv_bfloat16 h = __float2bfloat16(f);
    return *reinterpret_cast<unsigned short*>(&h);
}
static __device__ __forceinline__ float bff(unsigned short u) {
    __nv_bfloat16 h = *reinterpret_cast<__nv_bfloat16*>(&u);
    return __bfloat162float(h);
}

__global__ __launch_bounds__(256, 1)
void hmma_nt_split(const __nv_bfloat16* __restrict__ Ah, const __nv_bfloat16* __restrict__ Al,
                   const __nv_bfloat16* __restrict__ Bh, const __nv_bfloat16* __restrict__ Bl,
                   float* __restrict__ C, __nv_bfloat16* __restrict__ Ch,
                   __nv_bfloat16* __restrict__ Cl,
                   int K, int Nc, long long sA, long long sB, long long sC, int epi)
{
    extern __shared__ __align__(16) char smem[];
    const uint32_t sb = s2u(smem);
    const int tid = threadIdx.x;
    const int m0 = blockIdx.y * 128;
    const int n0 = blockIdx.x * 128;
    const int z = blockIdx.z;

    const __nv_bfloat16* mat[4];
    mat[0] = Ah + (size_t)z * sA + (size_t)m0 * K;
    mat[1] = Al + (size_t)z * sA + (size_t)m0 * K;
    mat[2] = Bh + (size_t)z * sB + (size_t)n0 * K;
    mat[3] = Bl + (size_t)z * sB + (size_t)n0 * K;

    // cp.async mapping: 8 ops/thread/stage (4 matrices x 2 row halves)
    const int crow = tid >> 2;          // 0..63
    const int cc4 = tid & 3;            // 16B chunk within 64B row segment

    // ldmatrix lane addressing
    const int lane = tid & 31;
    const int wrp = tid >> 5;
    const int wm = wrp & 3;             // 4 warps along M (32 rows each)
    const int wn = wrp >> 2;            // 2 warps along N (64 cols each)
    const int lr = lane & 15;
    const int lk = (lane >> 4) * 8;     // column offset (halves)

    uint32_t a_off[2], b_off[4];
#pragma unroll
    for (int mi = 0; mi < 2; mi++)
        a_off[mi] = (uint32_t)((wm * 32 + mi * 16 + lr) * (STRH * 2) + lk * 2);
#pragma unroll
    for (int nj = 0; nj < 4; nj++)
        b_off[nj] = (uint32_t)((wn * 64 + nj * 16 + lr) * (STRH * 2) + lk * 2);

    float acc[2][8][4];
#pragma unroll
    for (int mi = 0; mi < 2; mi++)
#pragma unroll
        for (int ni = 0; ni < 8; ni++)
#pragma unroll
            for (int q = 0; q < 4; q++) acc[mi][ni][q] = 0.f;

    const int niter = K / 32;

    // ---- prefetch stage 0 ----
    {
        uint32_t sbase = sb;
#pragma unroll
        for (int m = 0; m < 4; m++)
#pragma unroll
            for (int j = 0; j < 2; j++) {
                int row = crow + j * 64;
                cpa16(sbase + m * MATSZ + row * (STRH * 2) + cc4 * 16,
                      mat[m] + (size_t)row * K + cc4 * 8);
            }
        asm volatile("cp.async.commit_group;");
    }

    for (int kt = 0; kt < niter; kt++) {
        const int st = kt & 1;
        if (kt + 1 < niter) {
            uint32_t sbase = sb + ((kt + 1) & 1) * HSTAGE;
            int kof = (kt + 1) * 32;
#pragma unroll
            for (int m = 0; m < 4; m++)
#pragma unroll
                for (int j = 0; j < 2; j++) {
                    int row = crow + j * 64;
                    cpa16(sbase + m * MATSZ + row * (STRH * 2) + cc4 * 16,
                          mat[m] + (size_t)row * K + kof + cc4 * 8);
                }
            asm volatile("cp.async.commit_group;");
            asm volatile("cp.async.wait_group 1;");
        } else {
            asm volatile("cp.async.wait_group 0;");
        }
        __syncthreads();

        const uint32_t sbase = sb + st * HSTAGE;
#pragma unroll
        for (int ks = 0; ks < 2; ks++) {
            const uint32_t koff = ks * 32;    // 16 halves = 32 bytes
            uint32_t ah[2][4], alr[2][4], bhf[4][4], blf[4][4];
#pragma unroll
            for (int mi = 0; mi < 2; mi++) {
                ldm4(ah[mi], sbase + 0 * MATSZ + a_off[mi] + koff);
                ldm4(alr[mi], sbase + 1 * MATSZ + a_off[mi] + koff);
            }
#pragma unroll
            for (int nj = 0; nj < 4; nj++) {
                ldm4(bhf[nj], sbase + 2 * MATSZ + b_off[nj] + koff);
                ldm4(blf[nj], sbase + 3 * MATSZ + b_off[nj] + koff);
            }
#pragma unroll
            for (int mi = 0; mi < 2; mi++)
#pragma unroll
                for (int nj = 0; nj < 4; nj++)
#pragma unroll
                    for (int h = 0; h < 2; h++) {
                        float* d = acc[mi][nj * 2 + h];
                        mma16816(d, ah[mi], bhf[nj][h], bhf[nj][h + 2]);   // hi*hi
                        mma16816(d, ah[mi], blf[nj][h], blf[nj][h + 2]);   // hi*lo
                        mma16816(d, alr[mi], bhf[nj][h], bhf[nj][h + 2]);  // lo*hi
                    }
        }
        __syncthreads();
    }

    // ---- epilogue ----
    const int qrow = lane >> 2;         // 0..7
    const int qcol = (lane & 3) * 2;    // 0,2,4,6
    if (epi == 0) {
        float* Cb = C + (size_t)z * sC;
#pragma unroll
        for (int mi = 0; mi < 2; mi++) {
            int r0 = m0 + wm * 32 + mi * 16 + qrow;
#pragma unroll
            for (int ni = 0; ni < 8; ni++) {
                int cc = n0 + wn * 64 + ni * 8 + qcol;
                float* p0 = Cb + (size_t)r0 * Nc + cc;
                float* p1 = Cb + (size_t)(r0 + 8) * Nc + cc;
                *(float2*)p0 = make_float2(acc[mi][ni][0], acc[mi][ni][1]);
                *(float2*)p1 = make_float2(acc[mi][ni][2], acc[mi][ni][3]);
            }
        }
    } else {
#pragma unroll
        for (int mi = 0; mi < 2; mi++) {
            int r0 = m0 + wm * 32 + mi * 16 + qrow;
#pragma unroll
            for (int ni = 0; ni < 8; ni++) {
                int cc = n0 + wn * 64 + ni * 8 + qcol;
#pragma unroll
                for (int rh = 0; rh < 2; rh++) {
                    float f0 = acc[mi][ni][2 * rh + 0];
                    float f1 = acc[mi][ni][2 * rh + 1];
                    unsigned short h0 = bfu(f0), h1 = bfu(f1);
                    unsigned short l0 = bfu(f0 - bff(h0)), l1 = bfu(f1 - bff(h1));
                    size_t o = (size_t)(r0 + 8 * rh) * Nc + cc;
                    *(uint32_t*)(Ch + o) = (uint32_t)h0 | ((uint32_t)h1 << 16);
                    *(uint32_t*)(Cl + o) = (uint32_t)l0 | ((uint32_t)l1 << 16);
                }
            }
        }
    }
}

// ---------------------------------------------------------------------------
// Softmax row stats: per row (b,q) of g_S compute max and 1/sumexp
// ---------------------------------------------------------------------------
__global__ void row_stats_k()
{
    const int row = blockIdx.x;
    const float* r = g_S + (size_t)row * S_;
    const int tid = threadIdx.x;

    float v[8];
    float mx = -3.0e38f;
#pragma unroll
    for (int i = 0; i < 8; i++) {
        v[i] = r[i * 256 + tid];
        mx = fmaxf(mx, v[i]);
    }
    __shared__ float red[8];
#pragma unroll
    for (int o = 16; o > 0; o >>= 1) mx = fmaxf(mx, __shfl_xor_sync(0xffffffffu, mx, o));
    if ((tid & 31) == 0) red[tid >> 5] = mx;
    __syncthreads();
    float m = red[0];
#pragma unroll
    for (int w = 1; w < 8; w++) m = fmaxf(m, red[w]);
    __syncthreads();

    float s = 0.f;
#pragma unroll
    for (int i = 0; i < 8; i++) s += __expf(v[i] - m);
#pragma unroll
    for (int o = 16; o > 0; o >>= 1) s += __shfl_xor_sync(0xffffffffu, s, o);
    if ((tid & 31) == 0) red[tid >> 5] = s;
    __syncthreads();
    if (tid == 0) {
        float t = 0.f;
#pragma unroll
        for (int w = 0; w < 8; w++) t += red[w];
        g_m[row] = m;
        g_linv[row] = 1.0f / t;
    }
}

// ---------------------------------------------------------------------------
// Column sums of softmax: c[b,k] = sum_q exp(S[b,q,k]-m[b,q]) * linv[b,q]
// ---------------------------------------------------------------------------
__global__ void colsum_k()
{
    const int b = blockIdx.y;
    const int k = blockIdx.x * 256 + threadIdx.x;
    const float* Sb = g_S + (size_t)b * S_ * S_;
    const float* mb = g_m + b * S_;
    const float* lb = g_linv + b * S_;
    float acc = 0.f;
#pragma unroll 4
    for (int q = 0; q < S_; q++) {
        acc += __expf(Sb[(size_t)q * S_ + k] - mb[q]) * lb[q];
    }
    g_c[b * S_ + k] = acc;
}

// ---------------------------------------------------------------------------
// t = c @ X (partials over q-chunks), reduce, out = t @ Wv
// ---------------------------------------------------------------------------
__global__ void cx_k(const float* __restrict__ X)
{
    const int b = blockIdx.z;
    const int p = blockIdx.y;
    const int d = blockIdx.x * 256 + threadIdx.x;
    const float* Xb = X + (size_t)b * S_ * D_;
    const float* cb = g_c + b * S_;
    const int q0 = p * (S_ / QSPLIT);
    float acc = 0.f;
#pragma unroll 4
    for (int i = 0; i < S_ / QSPLIT; i++) {
        int q = q0 + i;
        acc += cb[q] * Xb[(size_t)q * D_ + d];
    }
    g_tp[(p * B_ + b) * D_ + d] = acc;
}

__global__ void reduce_t_k()
{
    const int b = blockIdx.x;
    const int d = threadIdx.x;
    float s = 0.f;
#pragma unroll
    for (int p = 0; p < QSPLIT; p++) s += g_tp[(p * B_ + b) * D_ + d];
    g_t[b * D_ + d] = s;
}

__global__ void out_k(const float* __restrict__ Wv, float* __restrict__ out)
{
    const int b = blockIdx.y;
    const int e = blockIdx.x * 128 + threadIdx.x;
    const float* tb = g_t + b * D_;
    float acc = 0.f;
#pragma unroll 8
    for (int d = 0; d < D_; d++)
        acc += tb[d] * Wv[(size_t)d * D_ + e];
    out[b * D_ + e] = acc;
}

// ---------------------------------------------------------------------------
// Launch: Gt = Wk Wq^T/sqrt(D); split X, Gt; H(split) = X @ Gt^T (HMMA);
//         S = H @ X^T (HMMA); softmax stats; colsum; t = c X; out = t Wv.
// ---------------------------------------------------------------------------
extern "C" void kernel_launch(void* const* d_in, const int* in_sizes, int n_in,
                              void* d_out, int out_size)
{
    const float* X  = (const float*)d_in[0];
    const float* Wq = (const float*)d_in[1];
    const float* Wk = (const float*)d_in[2];
    const float* Wv = (const float*)d_in[3];
    float* out = (float*)d_out;

    float *pG = nullptr, *pS = nullptr;
    __nv_bfloat16 *pXh, *pXl, *pHh, *pHl, *pGth, *pGtl;
    cudaGetSymbolAddress((void**)&pG, g_G);
    cudaGetSymbolAddress((void**)&pS, g_S);
    cudaGetSymbolAddress((void**)&pXh, g_Xh);
    cudaGetSymbolAddress((void**)&pXl, g_Xl);
    cudaGetSymbolAddress((void**)&pHh, g_Hh);
    cudaGetSymbolAddress((void**)&pHl, g_Hl);
    cudaGetSymbolAddress((void**)&pGth, g_Gth);
    cudaGetSymbolAddress((void**)&pGtl, g_Gtl);

    cudaFuncSetAttribute(hmma_nt_split, cudaFuncAttributeMaxDynamicSharedMemorySize, HSMEM);

    const float inv_sqrt_d = 1.0f / sqrtf((float)D_);

    // Gt = (Wk @ Wq^T) / sqrt(D)
    sgemm_nt_k<<<dim3(D_ / 128, D_ / 128, 1), 256>>>(Wk, Wq, pG, D_, D_, inv_sqrt_d);

    // bf16 hi/lo splits
    split4_k<<<(D_ * D_ / 4 + 255) / 256, 256>>>(
        (const float4*)pG, (__nv_bfloat162*)pGth, (__nv_bfloat162*)pGtl, D_ * D_ / 4);
    split4_k<<<(B_ * S_ * D_ / 4 + 255) / 256, 256>>>(
        (const float4*)X, (__nv_bfloat162*)pXh, (__nv_bfloat162*)pXl, B_ * S_ * D_ / 4);

    // H = X @ Gt^T  (HMMA split), epilogue writes bf16 hi/lo
    hmma_nt_split<<<dim3(D_ / 128, (B_ * S_) / 128, 1), 256, HSMEM>>>(
        pXh, pXl, pGth, pGtl, nullptr, pHh, pHl, D_, D_, 0, 0, 0, 1);

    // S_b = H_b @ X_b^T  (HMMA split), fp32 out (scale folded into Gt)
    hmma_nt_split<<<dim3(S_ / 128, S_ / 128, B_), 256, HSMEM>>>(
        pHh, pHl, pXh, pXl, pS, nullptr, nullptr, D_, S_,
        (long long)S_ * D_, (long long)S_ * D_, (long long)S_ * S_, 0);

    // Softmax row stats + column sums
    row_stats_k<<<B_ * S_, 256>>>();
    colsum_k<<<dim3(S_ / 256, B_), 256>>>();

    // t = c @ X, reduce, out = t @ Wv
    cx_k<<<dim3(D_ / 256, QSPLIT, B_), 256>>>(X);
    reduce_t_k<<<B_, D_>>>();
    out_k<<<dim3(D_ / 128, B_), 128>>>(Wv, out);
}

// round 17
// speedup vs baseline: 1.6050x; 1.0978x over previous
#include <cuda_runtime.h>
#include <cuda_bf16.h>
#include <stdint.h>
#include <math.h>

// Problem shape (fixed by the reference)
#define B_ 16
#define S_ 2048
#define D_ 512
#define QSPLIT 8

// ---------------------------------------------------------------------------
// Scratch (device globals: allocation-free per harness rules)
// ---------------------------------------------------------------------------
__device__ float g_G[D_ * D_];                        // Gt = Wk @ Wq^T / sqrt(D)
__device__ float g_S[67108864];                       // B*S*S scores (256 MB)
__device__ float g_m[B_ * S_];                        // row max
__device__ float g_linv[B_ * S_];                     // 1 / row sumexp
__device__ float g_c[B_ * S_];                        // column sums of softmax
__device__ float g_tp[QSPLIT * B_ * D_];              // partial c@X
__device__ float g_t[B_ * D_];                        // c@X
__device__ __nv_bfloat16 g_Xh[B_ * S_ * D_];          // X hi (32 MB)
__device__ __nv_bfloat16 g_Xl[B_ * S_ * D_];          // X lo
__device__ __nv_bfloat16 g_Hh[B_ * S_ * D_];          // H hi
__device__ __nv_bfloat16 g_Hl[B_ * S_ * D_];          // H lo
__device__ __nv_bfloat16 g_Gth[D_ * D_];              // Gt hi
__device__ __nv_bfloat16 g_Gtl[D_ * D_];              // Gt lo

// ---------------------------------------------------------------------------
// Packed f32x2 helpers (for the tiny fp32 Gt GEMM)
// ---------------------------------------------------------------------------
typedef unsigned long long u64;

__device__ __forceinline__ u64 ffma2(u64 a, u64 b, u64 c) {
    u64 r;
    asm("fma.rn.f32x2 %0, %1, %2, %3;" : "=l"(r) : "l"(a), "l"(b), "l"(c));
    return r;
}
__device__ __forceinline__ u64 fdup(float x) {
    u64 r;
    unsigned xi = __float_as_uint(x);
    asm("mov.b64 %0, {%1, %1};" : "=l"(r) : "r"(xi));
    return r;
}
__device__ __forceinline__ float2 unpack2(u64 v) {
    unsigned lo, hi;
    asm("mov.b64 {%0, %1}, %2;" : "=r"(lo), "=r"(hi) : "l"(v));
    return make_float2(__uint_as_float(lo), __uint_as_float(hi));
}

// ---------------------------------------------------------------------------
// fp32x2 SGEMM nt (only used for Gt = Wk @ Wq^T, 512x512)
// ---------------------------------------------------------------------------
#define TILE 128
#define BKD 8
#define SLD (TILE + 4)

__global__ __launch_bounds__(256, 2)
void sgemm_nt_k(const float* __restrict__ A, const float* __restrict__ Bm,
                float* __restrict__ C, int K, int N, float alpha)
{
    __shared__ __align__(16) float As[BKD][SLD];
    __shared__ __align__(16) float Bs[BKD][SLD];
    const int tid = threadIdx.x;
    const int tx = tid & 15;
    const int ty = tid >> 4;
    const int m0 = blockIdx.y * TILE;
    const int n0 = blockIdx.x * TILE;

    const int lrow = tid >> 1;
    const int lcol = (tid & 1) << 2;

    const float* Ap = A + (size_t)(m0 + lrow) * K + lcol;
    const float* Bp = Bm + (size_t)(n0 + lrow) * K + lcol;

    u64 acc[8][4];
#pragma unroll
    for (int i = 0; i < 8; i++)
#pragma unroll
        for (int j = 0; j < 4; j++) acc[i][j] = 0ull;

    float4 av = *(const float4*)(Ap);
    float4 bv = *(const float4*)(Bp);

    for (int k0 = 0; k0 < K; k0 += BKD) {
        As[lcol + 0][lrow] = av.x; As[lcol + 1][lrow] = av.y;
        As[lcol + 2][lrow] = av.z; As[lcol + 3][lrow] = av.w;
        Bs[lcol + 0][lrow] = bv.x; Bs[lcol + 1][lrow] = bv.y;
        Bs[lcol + 2][lrow] = bv.z; Bs[lcol + 3][lrow] = bv.w;
        __syncthreads();
        if (k0 + BKD < K) {
            av = *(const float4*)(Ap + k0 + BKD);
            bv = *(const float4*)(Bp + k0 + BKD);
        }
#pragma unroll
        for (int kk = 0; kk < BKD; kk++) {
            float4 a0 = *(const float4*)&As[kk][ty << 2];
            float4 a1 = *(const float4*)&As[kk][64 + (ty << 2)];
            const u64* bq0 = (const u64*)&Bs[kk][tx << 2];
            const u64* bq1 = (const u64*)&Bs[kk][64 + (tx << 2)];
            u64 b0 = bq0[0], b1 = bq0[1], b2 = bq1[0], b3 = bq1[1];
            float a[8] = {a0.x, a0.y, a0.z, a0.w, a1.x, a1.y, a1.z, a1.w};
#pragma unroll
            for (int i = 0; i < 8; i++) {
                u64 ad = fdup(a[i]);
                acc[i][0] = ffma2(ad, b0, acc[i][0]);
                acc[i][1] = ffma2(ad, b1, acc[i][1]);
                acc[i][2] = ffma2(ad, b2, acc[i][2]);
                acc[i][3] = ffma2(ad, b3, acc[i][3]);
            }
        }
        __syncthreads();
    }
#pragma unroll
    for (int i = 0; i < 8; i++) {
        int rr = (i < 4) ? ((ty << 2) + i) : ((ty << 2) + 60 + i);
        float* crow = C + (size_t)(m0 + rr) * N + n0;
        float2 p0 = unpack2(acc[i][0]), p1 = unpack2(acc[i][1]);
        float2 p2 = unpack2(acc[i][2]), p3 = unpack2(acc[i][3]);
        float4 v0 = make_float4(alpha * p0.x, alpha * p0.y, alpha * p1.x, alpha * p1.y);
        float4 v1 = make_float4(alpha * p2.x, alpha * p2.y, alpha * p3.x, alpha * p3.y);
        *(float4*)(crow + (tx << 2)) = v0;
        *(float4*)(crow + 64 + (tx << 2)) = v1;
    }
}

// ---------------------------------------------------------------------------
// fp32 -> bf16 hi/lo split (vectorized by 4)
// ---------------------------------------------------------------------------
__global__ void split4_k(const float4* __restrict__ src,
                         __nv_bfloat162* __restrict__ hi,
                         __nv_bfloat162* __restrict__ lo, int n4)
{
    int i = blockIdx.x * 256 + threadIdx.x;
    if (i >= n4) return;
    float4 v = src[i];
    __nv_bfloat16 h0 = __float2bfloat16(v.x), h1 = __float2bfloat16(v.y);
    __nv_bfloat16 h2 = __float2bfloat16(v.z), h3 = __float2bfloat16(v.w);
    __nv_bfloat16 l0 = __float2bfloat16(v.x - __bfloat162float(h0));
    __nv_bfloat16 l1 = __float2bfloat16(v.y - __bfloat162float(h1));
    __nv_bfloat16 l2 = __float2bfloat16(v.z - __bfloat162float(h2));
    __nv_bfloat16 l3 = __float2bfloat16(v.w - __bfloat162float(h3));
    __nv_bfloat162 a; a.x = h0; a.y = h1;
    __nv_bfloat162 b; b.x = h2; b.y = h3;
    __nv_bfloat162 c; c.x = l0; c.y = l1;
    __nv_bfloat162 d; d.x = l2; d.y = l3;
    hi[2 * i] = a; hi[2 * i + 1] = b;
    lo[2 * i] = c; lo[2 * i + 1] = d;
}

// ---------------------------------------------------------------------------
// HMMA (mma.sync m16n8k16 bf16) split NT GEMM.
// C = Ahi Bhi^T + Alo Bhi^T + Ahi Blo^T,  fp32 accumulate.
// A: [M,K] K-major, B: [N,K] K-major (both bf16 hi/lo).
// CTA tile 128x128, 8 warps = 4(M) x 2(N) -> warp tile 32x64.
// KC=32 double-buffered via cp.async; smem row stride 40 halves.
// Pass order hi*hi -> lo*hi -> hi*lo keeps fragment live ranges small so the
// kernel fits in <=128 regs (2 CTAs/SM via __launch_bounds__(256, 2)).
// epi=0: fp32 C out.  epi=1: bf16 hi/lo out (Ch/Cl).
// ---------------------------------------------------------------------------
#define STRH 40                       // halves per smem row
#define MATSZ (128 * STRH * 2)        // 10240 B per matrix tile
#define HSTAGE (4 * MATSZ)            // 40960 B per stage
#define HSMEM (2 * HSTAGE)            // 81920 B total

static __device__ __forceinline__ uint32_t s2u(const void* p) {
    uint32_t a;
    asm("{ .reg .u64 t; cvta.to.shared.u64 t, %1; cvt.u32.u64 %0, t; }" : "=r"(a) : "l"(p));
    return a;
}
static __device__ __forceinline__ void cpa16(uint32_t s, const void* g) {
    asm volatile("cp.async.cg.shared.global [%0], [%1], 16;" :: "r"(s), "l"(g));
}
static __device__ __forceinline__ void ldm4(uint32_t* r, uint32_t a) {
    asm volatile("ldmatrix.sync.aligned.m8n8.x4.shared.b16 {%0,%1,%2,%3}, [%4];"
                 : "=r"(r[0]), "=r"(r[1]), "=r"(r[2]), "=r"(r[3]) : "r"(a));
}
static __device__ __forceinline__ void mma16816(float* d, const uint32_t* a,
                                                uint32_t b0, uint32_t b1) {
    asm volatile("mma.sync.aligned.m16n8k16.row.col.f32.bf16.bf16.f32 "
                 "{%0,%1,%2,%3}, {%4,%5,%6,%7}, {%8,%9}, {%0,%1,%2,%3};"
                 : "+f"(d[0]), "+f"(d[1]), "+f"(d[2]), "+f"(d[3])
                 : "r"(a[0]), "r"(a[1]), "r"(a[2]), "r"(a[3]), "r"(b0), "r"(b1));
}
static __device__ __forceinline__ unsigned short bfu(float f) {
    __nv_bfloat16 h = __float2bfloat16(f);
    return *reinterpret_cast<unsigned short*>(&h);
}
static __device__ __forceinline__ float bff(unsigned short u) {
    __nv_bfloat16 h = *reinterpret_cast<__nv_bfloat16*>(&u);
    return __bfloat162float(h);
}

__global__ __launch_bounds__(256, 2)
void hmma_nt_split(const __nv_bfloat16* __restrict__ Ah, const __nv_bfloat16* __restrict__ Al,
                   const __nv_bfloat16* __restrict__ Bh, const __nv_bfloat16* __restrict__ Bl,
                   float* __restrict__ C, __nv_bfloat16* __restrict__ Ch,
                   __nv_bfloat16* __restrict__ Cl,
                   int K, int Nc, long long sA, long long sB, long long sC, int epi)
{
    extern __shared__ __align__(16) char smem[];
    const uint32_t sb = s2u(smem);
    const int tid = threadIdx.x;
    const int m0 = blockIdx.y * 128;
    const int n0 = blockIdx.x * 128;
    const int z = blockIdx.z;

    const __nv_bfloat16* mat[4];
    mat[0] = Ah + (size_t)z * sA + (size_t)m0 * K;
    mat[1] = Al + (size_t)z * sA + (size_t)m0 * K;
    mat[2] = Bh + (size_t)z * sB + (size_t)n0 * K;
    mat[3] = Bl + (size_t)z * sB + (size_t)n0 * K;

    // cp.async mapping: 8 ops/thread/stage (4 matrices x 2 row halves)
    const int crow = tid >> 2;          // 0..63
    const int cc4 = tid & 3;            // 16B chunk within 64B row segment

    // ldmatrix lane addressing
    const int lane = tid & 31;
    const int wrp = tid >> 5;
    const int wm = wrp & 3;             // 4 warps along M (32 rows each)
    const int wn = wrp >> 2;            // 2 warps along N (64 cols each)
    const int lr = lane & 15;
    const int lk = (lane >> 4) * 8;     // column offset (halves)

    uint32_t a_off[2], b_off[4];
#pragma unroll
    for (int mi = 0; mi < 2; mi++)
        a_off[mi] = (uint32_t)((wm * 32 + mi * 16 + lr) * (STRH * 2) + lk * 2);
#pragma unroll
    for (int nj = 0; nj < 4; nj++)
        b_off[nj] = (uint32_t)((wn * 64 + nj * 16 + lr) * (STRH * 2) + lk * 2);

    float acc[2][8][4];
#pragma unroll
    for (int mi = 0; mi < 2; mi++)
#pragma unroll
        for (int ni = 0; ni < 8; ni++)
#pragma unroll
            for (int q = 0; q < 4; q++) acc[mi][ni][q] = 0.f;

    const int niter = K / 32;

    // ---- prefetch stage 0 ----
    {
        uint32_t sbase = sb;
#pragma unroll
        for (int m = 0; m < 4; m++)
#pragma unroll
            for (int j = 0; j < 2; j++) {
                int row = crow + j * 64;
                cpa16(sbase + m * MATSZ + row * (STRH * 2) + cc4 * 16,
                      mat[m] + (size_t)row * K + cc4 * 8);
            }
        asm volatile("cp.async.commit_group;");
    }

    for (int kt = 0; kt < niter; kt++) {
        const int st = kt & 1;
        if (kt + 1 < niter) {
            uint32_t sbase = sb + ((kt + 1) & 1) * HSTAGE;
            int kof = (kt + 1) * 32;
#pragma unroll
            for (int m = 0; m < 4; m++)
#pragma unroll
                for (int j = 0; j < 2; j++) {
                    int row = crow + j * 64;
                    cpa16(sbase + m * MATSZ + row * (STRH * 2) + cc4 * 16,
                          mat[m] + (size_t)row * K + kof + cc4 * 8);
                }
            asm volatile("cp.async.commit_group;");
            asm volatile("cp.async.wait_group 1;");
        } else {
            asm volatile("cp.async.wait_group 0;");
        }
        __syncthreads();

        const uint32_t sbase = sb + st * HSTAGE;
#pragma unroll
        for (int ks = 0; ks < 2; ks++) {
            const uint32_t koff = ks * 32;    // 16 halves = 32 bytes

            // Pass 1: hi*hi  (ah, bh live)
            uint32_t ah[2][4], bh[4][4];
#pragma unroll
            for (int mi = 0; mi < 2; mi++)
                ldm4(ah[mi], sbase + 0 * MATSZ + a_off[mi] + koff);
#pragma unroll
            for (int nj = 0; nj < 4; nj++)
                ldm4(bh[nj], sbase + 2 * MATSZ + b_off[nj] + koff);
#pragma unroll
            for (int mi = 0; mi < 2; mi++)
#pragma unroll
                for (int nj = 0; nj < 4; nj++)
#pragma unroll
                    for (int h = 0; h < 2; h++)
                        mma16816(acc[mi][nj * 2 + h], ah[mi], bh[nj][h], bh[nj][h + 2]);

            // Pass 2: lo*hi  (al joins; bh dies after this pass)
            {
                uint32_t al[2][4];
#pragma unroll
                for (int mi = 0; mi < 2; mi++)
                    ldm4(al[mi], sbase + 1 * MATSZ + a_off[mi] + koff);
#pragma unroll
                for (int mi = 0; mi < 2; mi++)
#pragma unroll
                    for (int nj = 0; nj < 4; nj++)
#pragma unroll
                        for (int h = 0; h < 2; h++)
                            mma16816(acc[mi][nj * 2 + h], al[mi], bh[nj][h], bh[nj][h + 2]);
            }

            // Pass 3: hi*lo  (bl replaces bh/al)
            {
                uint32_t bl[4][4];
#pragma unroll
                for (int nj = 0; nj < 4; nj++)
                    ldm4(bl[nj], sbase + 3 * MATSZ + b_off[nj] + koff);
#pragma unroll
                for (int mi = 0; mi < 2; mi++)
#pragma unroll
                    for (int nj = 0; nj < 4; nj++)
#pragma unroll
                        for (int h = 0; h < 2; h++)
                            mma16816(acc[mi][nj * 2 + h], ah[mi], bl[nj][h], bl[nj][h + 2]);
            }
        }
        __syncthreads();
    }

    // ---- epilogue ----
    const int qrow = lane >> 2;         // 0..7
    const int qcol = (lane & 3) * 2;    // 0,2,4,6
    if (epi == 0) {
        float* Cb = C + (size_t)z * sC;
#pragma unroll
        for (int mi = 0; mi < 2; mi++) {
            int r0 = m0 + wm * 32 + mi * 16 + qrow;
#pragma unroll
            for (int ni = 0; ni < 8; ni++) {
                int cc = n0 + wn * 64 + ni * 8 + qcol;
                float* p0 = Cb + (size_t)r0 * Nc + cc;
                float* p1 = Cb + (size_t)(r0 + 8) * Nc + cc;
                *(float2*)p0 = make_float2(acc[mi][ni][0], acc[mi][ni][1]);
                *(float2*)p1 = make_float2(acc[mi][ni][2], acc[mi][ni][3]);
            }
        }
    } else {
#pragma unroll
        for (int mi = 0; mi < 2; mi++) {
            int r0 = m0 + wm * 32 + mi * 16 + qrow;
#pragma unroll
            for (int ni = 0; ni < 8; ni++) {
                int cc = n0 + wn * 64 + ni * 8 + qcol;
#pragma unroll
                for (int rh = 0; rh < 2; rh++) {
                    float f0 = acc[mi][ni][2 * rh + 0];
                    float f1 = acc[mi][ni][2 * rh + 1];
                    unsigned short h0 = bfu(f0), h1 = bfu(f1);
                    unsigned short l0 = bfu(f0 - bff(h0)), l1 = bfu(f1 - bff(h1));
                    size_t o = (size_t)(r0 + 8 * rh) * Nc + cc;
                    *(uint32_t*)(Ch + o) = (uint32_t)h0 | ((uint32_t)h1 << 16);
                    *(uint32_t*)(Cl + o) = (uint32_t)l0 | ((uint32_t)l1 << 16);
                }
            }
        }
    }
}

// ---------------------------------------------------------------------------
// Softmax row stats: per row (b,q) of g_S compute max and 1/sumexp
// ---------------------------------------------------------------------------
__global__ void row_stats_k()
{
    const int row = blockIdx.x;
    const float* r = g_S + (size_t)row * S_;
    const int tid = threadIdx.x;

    float v[8];
    float mx = -3.0e38f;
#pragma unroll
    for (int i = 0; i < 8; i++) {
        v[i] = r[i * 256 + tid];
        mx = fmaxf(mx, v[i]);
    }
    __shared__ float red[8];
#pragma unroll
    for (int o = 16; o > 0; o >>= 1) mx = fmaxf(mx, __shfl_xor_sync(0xffffffffu, mx, o));
    if ((tid & 31) == 0) red[tid >> 5] = mx;
    __syncthreads();
    float m = red[0];
#pragma unroll
    for (int w = 1; w < 8; w++) m = fmaxf(m, red[w]);
    __syncthreads();

    float s = 0.f;
#pragma unroll
    for (int i = 0; i < 8; i++) s += __expf(v[i] - m);
#pragma unroll
    for (int o = 16; o > 0; o >>= 1) s += __shfl_xor_sync(0xffffffffu, s, o);
    if ((tid & 31) == 0) red[tid >> 5] = s;
    __syncthreads();
    if (tid == 0) {
        float t = 0.f;
#pragma unroll
        for (int w = 0; w < 8; w++) t += red[w];
        g_m[row] = m;
        g_linv[row] = 1.0f / t;
    }
}

// ---------------------------------------------------------------------------
// Column sums of softmax: c[b,k] = sum_q exp(S[b,q,k]-m[b,q]) * linv[b,q]
// ---------------------------------------------------------------------------
__global__ void colsum_k()
{
    const int b = blockIdx.y;
    const int k = blockIdx.x * 256 + threadIdx.x;
    const float* Sb = g_S + (size_t)b * S_ * S_;
    const float* mb = g_m + b * S_;
    const float* lb = g_linv + b * S_;
    float acc = 0.f;
#pragma unroll 4
    for (int q = 0; q < S_; q++) {
        acc += __expf(Sb[(size_t)q * S_ + k] - mb[q]) * lb[q];
    }
    g_c[b * S_ + k] = acc;
}

// ---------------------------------------------------------------------------
// t = c @ X (partials over q-chunks), reduce, out = t @ Wv
// ---------------------------------------------------------------------------
__global__ void cx_k(const float* __restrict__ X)
{
    const int b = blockIdx.z;
    const int p = blockIdx.y;
    const int d = blockIdx.x * 256 + threadIdx.x;
    const float* Xb = X + (size_t)b * S_ * D_;
    const float* cb = g_c + b * S_;
    const int q0 = p * (S_ / QSPLIT);
    float acc = 0.f;
#pragma unroll 4
    for (int i = 0; i < S_ / QSPLIT; i++) {
        int q = q0 + i;
        acc += cb[q] * Xb[(size_t)q * D_ + d];
    }
    g_tp[(p * B_ + b) * D_ + d] = acc;
}

__global__ void reduce_t_k()
{
    const int b = blockIdx.x;
    const int d = threadIdx.x;
    float s = 0.f;
#pragma unroll
    for (int p = 0; p < QSPLIT; p++) s += g_tp[(p * B_ + b) * D_ + d];
    g_t[b * D_ + d] = s;
}

__global__ void out_k(const float* __restrict__ Wv, float* __restrict__ out)
{
    const int b = blockIdx.y;
    const int e = blockIdx.x * 128 + threadIdx.x;
    const float* tb = g_t + b * D_;
    float acc = 0.f;
#pragma unroll 8
    for (int d = 0; d < D_; d++)
        acc += tb[d] * Wv[(size_t)d * D_ + e];
    out[b * D_ + e] = acc;
}

// ---------------------------------------------------------------------------
// Launch: Gt = Wk Wq^T/sqrt(D); split X, Gt; H(split) = X @ Gt^T (HMMA);
//         S = H @ X^T (HMMA); softmax stats; colsum; t = c X; out = t Wv.
// ---------------------------------------------------------------------------
extern "C" void kernel_launch(void* const* d_in, const int* in_sizes, int n_in,
                              void* d_out, int out_size)
{
    const float* X  = (const float*)d_in[0];
    const float* Wq = (const float*)d_in[1];
    const float* Wk = (const float*)d_in[2];
    const float* Wv = (const float*)d_in[3];
    float* out = (float*)d_out;

    float *pG = nullptr, *pS = nullptr;
    __nv_bfloat16 *pXh, *pXl, *pHh, *pHl, *pGth, *pGtl;
    cudaGetSymbolAddress((void**)&pG, g_G);
    cudaGetSymbolAddress((void**)&pS, g_S);
    cudaGetSymbolAddress((void**)&pXh, g_Xh);
    cudaGetSymbolAddress((void**)&pXl, g_Xl);
    cudaGetSymbolAddress((void**)&pHh, g_Hh);
    cudaGetSymbolAddress((void**)&pHl, g_Hl);
    cudaGetSymbolAddress((void**)&pGth, g_Gth);
    cudaGetSymbolAddress((void**)&pGtl, g_Gtl);

    cudaFuncSetAttribute(hmma_nt_split, cudaFuncAttributeMaxDynamicSharedMemorySize, HSMEM);

    const float inv_sqrt_d = 1.0f / sqrtf((float)D_);

    // Gt = (Wk @ Wq^T) / sqrt(D)
    sgemm_nt_k<<<dim3(D_ / 128, D_ / 128, 1), 256>>>(Wk, Wq, pG, D_, D_, inv_sqrt_d);

    // bf16 hi/lo splits
    split4_k<<<(D_ * D_ / 4 + 255) / 256, 256>>>(
        (const float4*)pG, (__nv_bfloat162*)pGth, (__nv_bfloat162*)pGtl, D_ * D_ / 4);
    split4_k<<<(B_ * S_ * D_ / 4 + 255) / 256, 256>>>(
        (const float4*)X, (__nv_bfloat162*)pXh, (__nv_bfloat162*)pXl, B_ * S_ * D_ / 4);

    // H = X @ Gt^T  (HMMA split), epilogue writes bf16 hi/lo
    hmma_nt_split<<<dim3(D_ / 128, (B_ * S_) / 128, 1), 256, HSMEM>>>(
        pXh, pXl, pGth, pGtl, nullptr, pHh, pHl, D_, D_, 0, 0, 0, 1);

    // S_b = H_b @ X_b^T  (HMMA split), fp32 out (scale folded into Gt)
    hmma_nt_split<<<dim3(S_ / 128, S_ / 128, B_), 256, HSMEM>>>(
        pHh, pHl, pXh, pXl, pS, nullptr, nullptr, D_, S_,
        (long long)S_ * D_, (long long)S_ * D_, (long long)S_ * S_, 0);

    // Softmax row stats + column sums
    row_stats_k<<<B_ * S_, 256>>>();
    colsum_k<<<dim3(S_ / 256, B_), 256>>>();

    // t = c @ X, reduce, out = t @ Wv
    cx_k<<<dim3(D_ / 256, QSPLIT, B_), 256>>>(X);
    reduce_t_k<<<B_, D_>>>();
    out_k<<<dim3(D_ / 128, B_), 128>>>(Wv, out);
}